// round 11
// baseline (speedup 1.0000x reference)
#include <cuda_runtime.h>
#include <cuda_bf16.h>
#include <cstddef>
#include <cstdint>

#define SPI 9
#define BM  128

// Activations stored pre-split: per vertex [hi bf16 x C | lo bf16 x C].
__device__ __align__(16) __nv_bfloat16 g_bufX[(size_t)8 * 50000 * 128]; // L0 out (64B/row) / L2 out (256B/row)
__device__ __align__(16) __nv_bfloat16 g_bufY[(size_t)8 * 50000 * 64];  // L1 out (128B/row)
// Weights pre-shuffled into mma.sync B-fragment order:
//   WF[s][kc][ngg][h][lane] : uint4 = {b_n0_klo, b_n8_klo, b_n0_khi, b_n8_khi}
__device__ __align__(16) uint4 g_WF1[9 * 1 * 2 * 2 * 32];
__device__ __align__(16) uint4 g_WF2[9 * 2 * 4 * 2 * 32];
__device__ __align__(16) uint4 g_WF3[9 * 4 * 8 * 2 * 32];

__device__ __forceinline__ void ffma2(float2 &d, const float2 &a, const float2 &b) {
    unsigned long long       &du = reinterpret_cast<unsigned long long &>(d);
    const unsigned long long &au = reinterpret_cast<const unsigned long long &>(a);
    const unsigned long long &bu = reinterpret_cast<const unsigned long long &>(b);
    asm("fma.rn.f32x2 %0, %1, %2, %0;" : "+l"(du) : "l"(au), "l"(bu));
}
__device__ __forceinline__ uint32_t smem_u32(const void *p) {
    uint32_t a;
    asm("{ .reg .u64 t; cvta.to.shared.u64 t, %1; cvt.u32.u64 %0, t; }" : "=r"(a) : "l"(p));
    return a;
}
#define SMEM_SWIZZLE_128B(o) ((o) ^ (((o) >> 3) & 0x70))

__device__ __forceinline__ void cp16(uint32_t dst, const void *src) {
    asm volatile("cp.async.cg.shared.global [%0], [%1], 16;" :: "r"(dst), "l"(src));
}
#define CP_COMMIT() asm volatile("cp.async.commit_group;" ::: "memory")
#define CP_WAIT0()  asm volatile("cp.async.wait_group 0;" ::: "memory")

__device__ __forceinline__ void ldmx4(uint32_t &r0, uint32_t &r1, uint32_t &r2,
                                      uint32_t &r3, uint32_t addr) {
    asm volatile("ldmatrix.sync.aligned.m8n8.x4.shared.b16 {%0,%1,%2,%3}, [%4];"
                 : "=r"(r0), "=r"(r1), "=r"(r2), "=r"(r3) : "r"(addr));
}
__device__ __forceinline__ void mma16816(float *c, const uint32_t *a,
                                         uint32_t b0, uint32_t b1) {
    asm volatile("mma.sync.aligned.m16n8k16.row.col.f32.bf16.bf16.f32 "
                 "{%0,%1,%2,%3}, {%4,%5,%6,%7}, {%8,%9}, {%0,%1,%2,%3};"
                 : "+f"(c[0]), "+f"(c[1]), "+f"(c[2]), "+f"(c[3])
                 : "r"(a[0]), "r"(a[1]), "r"(a[2]), "r"(a[3]), "r"(b0), "r"(b1));
}
__device__ __forceinline__ void split2(float2 v, uint32_t &h, uint32_t &l) {
    __nv_bfloat162 hb = __float22bfloat162_rn(v);
    float2 hf = __bfloat1622float2(hb);
    __nv_bfloat162 lb = __float22bfloat162_rn(make_float2(v.x - hf.x, v.y - hf.y));
    h = *(uint32_t *)&hb;
    l = *(uint32_t *)&lb;
}

// ---------------------------------------------------------------------------
// Layer 0 (FFMA2): Cin=3 -> 16, writes pre-split hi/lo rows (64B/vertex).
// ---------------------------------------------------------------------------
__global__ void layer0_kernel(const float *__restrict__ X, const int *__restrict__ idx,
                              const float *__restrict__ W, const float *__restrict__ bias,
                              __nv_bfloat16 *__restrict__ Y, int N) {
    __shared__ float Ws[27 * 16];
    __shared__ float bs[16];
    int tid = threadIdx.x;
    for (int t = tid; t < 27 * 16; t += blockDim.x) Ws[t] = W[t];
    if (tid < 16) bs[tid] = bias[tid];
    __syncthreads();

    int n = blockIdx.x * blockDim.x + tid;
    int b = blockIdx.y;
    if (n >= N) return;

    float2 acc[8];
#pragma unroll
    for (int j = 0; j < 8; j++) acc[j] = make_float2(bs[2 * j], bs[2 * j + 1]);

    const float *Xb = X + (size_t)b * N * 3;
#pragma unroll
    for (int s = 0; s < SPI; s++) {
        int r = idx[n * SPI + s];
        float xv[3];
        xv[0] = __ldg(Xb + (size_t)r * 3 + 0);
        xv[1] = __ldg(Xb + (size_t)r * 3 + 1);
        xv[2] = __ldg(Xb + (size_t)r * 3 + 2);
#pragma unroll
        for (int c = 0; c < 3; c++) {
            const float *wrow = Ws + (s * 3 + c) * 16;
            float2 vv = make_float2(xv[c], xv[c]);
#pragma unroll
            for (int j = 0; j < 8; j++) {
                float2 w = *(const float2 *)(wrow + 2 * j);
                ffma2(acc[j], vv, w);
            }
        }
    }
    uint32_t hi[8], lo[8];
#pragma unroll
    for (int j = 0; j < 8; j++) split2(acc[j], hi[j], lo[j]);
    char *y = (char *)Y + ((size_t)b * N + n) * 64;
    *(uint4 *)(y + 0)  = make_uint4(hi[0], hi[1], hi[2], hi[3]);
    *(uint4 *)(y + 16) = make_uint4(hi[4], hi[5], hi[6], hi[7]);
    *(uint4 *)(y + 32) = make_uint4(lo[0], lo[1], lo[2], lo[3]);
    *(uint4 *)(y + 48) = make_uint4(lo[4], lo[5], lo[6], lo[7]);
}

// ---------------------------------------------------------------------------
// Weight prep: W[S*CIN, COUT] -> mma B-fragment order, bf16 hi/lo.
// ---------------------------------------------------------------------------
template <int CIN, int COUT>
__global__ void prep_wfrag(const float *__restrict__ W, uint4 *__restrict__ dst) {
    constexpr int KCH = CIN / 16, NGT = COUT / 16;
    constexpr int PER = KCH * NGT * 64;
    int s = blockIdx.x;
    for (int i = threadIdx.x; i < PER; i += blockDim.x) {
        int lane = i & 31, h = (i >> 5) & 1, ngg = (i >> 6) % NGT, kc = (i >> 6) / NGT;
        int n0 = ngg * 16 + (lane >> 2);
        int kb = kc * 16 + 2 * (lane & 3);
        auto wsel = [&](int k, int n) -> uint32_t {
            float v = __ldg(W + (size_t)(s * CIN + k) * COUT + n);
            __nv_bfloat16 hb = __float2bfloat16_rn(v);
            if (h == 0) return (uint32_t)(*(uint16_t *)&hb);
            float r = v - __bfloat162float(hb);
            __nv_bfloat16 lb = __float2bfloat16_rn(r);
            return (uint32_t)(*(uint16_t *)&lb);
        };
        auto word = [&](int k, int n) { return wsel(k, n) | (wsel(k + 1, n) << 16); };
        uint4 q;
        q.x = word(kb,     n0);
        q.y = word(kb,     n0 + 8);
        q.z = word(kb + 8, n0);
        q.w = word(kb + 8, n0 + 8);
        dst[(size_t)s * PER + i] = q;
    }
}

// ---------------------------------------------------------------------------
// Unified spiral-conv layer: bf16x3 mma.sync.
// A via cp.async double-buffered gather, SPG = 64/CIN spiral steps PACKED per
// 128B smem row (stage) -> every full stage = exactly 4 k-chunks; barriers
// drop 9->3 (L1), 9->5 (L2), unchanged for L3. B via per-lane LDG fragments.
// ---------------------------------------------------------------------------
template <int CIN, int COUT, bool FUSE>
__global__ void __launch_bounds__(256, 2)
layer_mma(const __nv_bfloat16 *__restrict__ X,
          const int   *__restrict__ idxg,
          const float *__restrict__ bias,
          const uint4 *__restrict__ WF,
          const float *__restrict__ Wf,
          const float *__restrict__ bf,
          void *__restrict__ Y,
          int N) {
    constexpr int KCH = CIN / 16;
    constexpr int NGT = COUT / 16;
    constexpr int WN  = (COUT >= 128) ? 2 : 1;
    constexpr int WM  = 8 / WN;
    constexpr int MT  = 128 / (WM * 16);
    constexpr int NG  = NGT / WN;
    constexpr int CB  = 2 * CIN;              // bytes per hi segment per step
    constexpr int CPT = CB / 32;              // 16B chunks per thread per step
    constexpr int XROW = 4 * CIN;
    constexpr int SPG  = 64 / CIN;            // spiral steps packed per stage
    constexpr int NSTG = (SPI + SPG - 1) / SPG;
    constexpr int IDXOFF = 65536;             // A: hi st0/st1 (32KB), lo st0/st1
    constexpr int PRM = IDXOFF + 4608;
    constexpr int CSTR = 132;

    extern __shared__ __align__(1024) char smc[];
    uint32_t sb = smem_u32(smc);
    int tid = threadIdx.x, wid = tid >> 5, lane = tid & 31;
    int b = blockIdx.y, row0 = blockIdx.x * BM;
    int warpM = wid / WN, warpN = wid % WN;

    int *idxs = (int *)(smc + IDXOFF);
    for (int t = tid; t < SPI * BM; t += 256) {
        int m = t / SPI, s = t % SPI;
        int r = row0 + m;
        if (r >= N) r = N - 1;
        idxs[s * BM + m] = idxg[(size_t)r * SPI + s];
    }
    float *prm = (float *)(smc + PRM);
    if (FUSE) {
        for (int t = tid; t < 384; t += 256) prm[t] = Wf[t];
        if (tid < 3)    prm[384 + tid] = bf[tid];
        if (tid < COUT) prm[388 + tid] = bias[tid];
    } else {
        if (tid < COUT) prm[tid] = bias[tid];
    }

    float acc[MT][2 * NG][4];
#pragma unroll
    for (int mt = 0; mt < MT; mt++)
#pragma unroll
        for (int nf = 0; nf < 2 * NG; nf++)
#pragma unroll
            for (int c = 0; c < 4; c++) acc[mt][nf][c] = 0.0f;

    const char *Xb = (const char *)X + (size_t)b * N * XROW;
    int grow = tid >> 1, ghalf = tid & 1;
    uint32_t lm_row  = (uint32_t)(lane & 15);
    uint32_t lm_half = (uint32_t)(lane >> 4) << 4;

    __syncthreads();   // idxs ready

    // gather SPG steps' rows into packed segments of one 128B row
    auto issueA = [&](int stage, int st) {
        int s0 = stage * SPG;
        uint32_t ah = sb + (uint32_t)st * 16384;
        uint32_t al = sb + 32768 + (uint32_t)st * 16384;
#pragma unroll
        for (int j = 0; j < SPG; j++) {
            int s = s0 + j;
            if (s >= SPI) break;
            int r = idxs[s * BM + grow];
            const char *src = Xb + (size_t)r * XROW;
#pragma unroll
            for (int q = 0; q < CPT; q++) {
                int c16 = ghalf * CPT + q;                       // 16B chunk in segment
                uint32_t bo = (uint32_t)(grow * 128 + j * CB + 16 * c16);
                uint32_t so = SMEM_SWIZZLE_128B(bo);
                cp16(ah + so, src + 16 * c16);
                cp16(al + so, src + CB + 16 * c16);
            }
        }
    };

    issueA(0, 0);
    CP_COMMIT();

    for (int stage = 0; stage < NSTG; stage++) {
        int st = stage & 1;
        CP_WAIT0();
        __syncthreads();
        if (stage + 1 < NSTG) {
            issueA(stage + 1, st ^ 1);
            CP_COMMIT();
        }
        uint32_t aH = sb + (uint32_t)st * 16384;
        uint32_t aL = sb + 32768 + (uint32_t)st * 16384;
        int s0 = stage * SPG;
        int steps = SPI - s0; if (steps > SPG) steps = SPG;
        int kcmax = steps * KCH;                // full stage: 4
#pragma unroll
        for (int kc = 0; kc < SPG * KCH; kc++) {
            if (kc >= kcmax) break;
            int s_eff = s0 + kc / KCH;
            int kcw   = kc % KCH;
            uint32_t kcoff = (uint32_t)kc * 32 + lm_half;
            uint32_t Ah[MT][4], Al[MT][4];
#pragma unroll
            for (int mt = 0; mt < MT; mt++) {
                uint32_t ro = (uint32_t)(warpM * (16 * MT) + mt * 16 + lm_row) * 128 + kcoff;
                uint32_t so = SMEM_SWIZZLE_128B(ro);
                ldmx4(Ah[mt][0], Ah[mt][1], Ah[mt][2], Ah[mt][3], aH + so);
                ldmx4(Al[mt][0], Al[mt][1], Al[mt][2], Al[mt][3], aL + so);
            }
#pragma unroll
            for (int ng = 0; ng < NG; ng++) {
                int ngg = warpN * NG + ng;
                const uint4 *bp = WF + ((((size_t)s_eff * KCH + kcw) * NGT + ngg) * 2) * 32 + lane;
                uint4 qh = __ldg(bp);
                uint4 ql = __ldg(bp + 32);
#pragma unroll
                for (int mt = 0; mt < MT; mt++) {
                    mma16816(acc[mt][2 * ng],     Ah[mt], qh.x, qh.z);
                    mma16816(acc[mt][2 * ng + 1], Ah[mt], qh.y, qh.w);
                    mma16816(acc[mt][2 * ng],     Ah[mt], ql.x, ql.z);
                    mma16816(acc[mt][2 * ng + 1], Ah[mt], ql.y, ql.w);
                    mma16816(acc[mt][2 * ng],     Al[mt], qh.x, qh.z);
                    mma16816(acc[mt][2 * ng + 1], Al[mt], qh.y, qh.w);
                }
            }
        }
    }

    if (!FUSE) {
        char *Yb = (char *)Y + (size_t)b * N * (4 * COUT);
#pragma unroll
        for (int mt = 0; mt < MT; mt++) {
            int rr = row0 + warpM * (16 * MT) + mt * 16 + (lane >> 2);
#pragma unroll
            for (int nf = 0; nf < 2 * NG; nf++) {
                int c = warpN * (COUT / WN) + nf * 8 + (lane & 3) * 2;
                float bv0 = prm[c], bv1 = prm[c + 1];
                uint32_t h, l;
                if (rr < N) {
                    split2(make_float2(acc[mt][nf][0] + bv0, acc[mt][nf][1] + bv1), h, l);
                    char *rp = Yb + (size_t)rr * (4 * COUT);
                    *(uint32_t *)(rp + 2 * c) = h;
                    *(uint32_t *)(rp + 2 * COUT + 2 * c) = l;
                }
                if (rr + 8 < N) {
                    split2(make_float2(acc[mt][nf][2] + bv0, acc[mt][nf][3] + bv1), h, l);
                    char *rp = Yb + (size_t)(rr + 8) * (4 * COUT);
                    *(uint32_t *)(rp + 2 * c) = h;
                    *(uint32_t *)(rp + 2 * COUT + 2 * c) = l;
                }
            }
        }
    } else {
        __syncthreads();
        float *Cs = (float *)smc;   // [128][CSTR] = 67584B; overlaps dead A+idx, not prm
#pragma unroll
        for (int mt = 0; mt < MT; mt++) {
            int r = warpM * (16 * MT) + mt * 16 + (lane >> 2);
#pragma unroll
            for (int nf = 0; nf < 2 * NG; nf++) {
                int c = warpN * (COUT / WN) + nf * 8 + (lane & 3) * 2;
                Cs[r * CSTR + c]           = acc[mt][nf][0] + prm[388 + c];
                Cs[r * CSTR + c + 1]       = acc[mt][nf][1] + prm[388 + c + 1];
                Cs[(r + 8) * CSTR + c]     = acc[mt][nf][2] + prm[388 + c];
                Cs[(r + 8) * CSTR + c + 1] = acc[mt][nf][3] + prm[388 + c + 1];
            }
        }
        __syncthreads();
        if (tid < BM) {
            int r = row0 + tid;
            float o0 = prm[384], o1 = prm[385], o2 = prm[386];
            const float *crow = Cs + tid * CSTR;
#pragma unroll 16
            for (int k = 0; k < COUT; k++) {
                float v = crow[k];
                o0 = fmaf(v, prm[3 * k + 0], o0);
                o1 = fmaf(v, prm[3 * k + 1], o1);
                o2 = fmaf(v, prm[3 * k + 2], o2);
            }
            if (r < N) {
                float *o = (float *)Y + ((size_t)b * N + r) * 3;
                o[0] = o0; o[1] = o1; o[2] = o2;
            }
        }
    }
}

// ---------------------------------------------------------------------------
extern "C" void kernel_launch(void *const *d_in, const int *in_sizes, int n_in,
                              void *d_out, int out_size) {
    const float *x   = (const float *)d_in[0];
    const int   *idx = (const int *)d_in[1];
    const float *W0  = (const float *)d_in[2];
    const float *b0  = (const float *)d_in[3];
    const float *W1  = (const float *)d_in[4];
    const float *b1  = (const float *)d_in[5];
    const float *W2  = (const float *)d_in[6];
    const float *b2  = (const float *)d_in[7];
    const float *W3  = (const float *)d_in[8];
    const float *b3  = (const float *)d_in[9];
    const float *Wf  = (const float *)d_in[10];
    const float *bf  = (const float *)d_in[11];
    float *out = (float *)d_out;

    int N = in_sizes[1] / SPI;
    int B = in_sizes[0] / (N * 3);

    __nv_bfloat16 *bufX, *bufY;
    cudaGetSymbolAddress((void **)&bufX, g_bufX);
    cudaGetSymbolAddress((void **)&bufY, g_bufY);
    uint4 *wf1, *wf2, *wf3;
    cudaGetSymbolAddress((void **)&wf1, g_WF1);
    cudaGetSymbolAddress((void **)&wf2, g_WF2);
    cudaGetSymbolAddress((void **)&wf3, g_WF3);

    constexpr int SMN1 = 65536 + 4608 + 32 * 4;
    constexpr int SMN2 = 65536 + 4608 + 64 * 4;
    constexpr int SMF  = 65536 + 4608 + (384 + 4 + 128) * 4;
    cudaFuncSetAttribute(layer_mma<16, 32, false>,
                         cudaFuncAttributeMaxDynamicSharedMemorySize, SMN1);
    cudaFuncSetAttribute(layer_mma<32, 64, false>,
                         cudaFuncAttributeMaxDynamicSharedMemorySize, SMN2);
    cudaFuncSetAttribute(layer_mma<64, 128, true>,
                         cudaFuncAttributeMaxDynamicSharedMemorySize, SMF);

    prep_wfrag<16, 32><<<9, 256>>>(W1, wf1);
    prep_wfrag<32, 64><<<9, 256>>>(W2, wf2);
    prep_wfrag<64, 128><<<9, 256>>>(W3, wf3);

    dim3 g0((N + 255) / 256, B);
    layer0_kernel<<<g0, 256>>>(x, idx, W0, b0, bufX, N);

    dim3 gl((N + BM - 1) / BM, B);
    layer_mma<16, 32, false><<<gl, 256, SMN1>>>(bufX, idx, b1, wf1,
                                                nullptr, nullptr, bufY, N);
    layer_mma<32, 64, false><<<gl, 256, SMN2>>>(bufY, idx, b2, wf2,
                                                nullptr, nullptr, bufX, N);
    layer_mma<64, 128, true><<<gl, 256, SMF>>>(bufX, idx, b3, wf3,
                                               Wf, bf, out, N);
}